// round 9
// baseline (speedup 1.0000x reference)
#include <cuda_runtime.h>
#include <cstdint>

#define BATCH 4
#define NPTS 4096
#define KOUT 16
#define NEED 31                 // rank 0 plus ranks 16..30
#define R2 256.0f
#define NTILES (NPTS / 32)      // 128
#define TPB 512
#define WARPS (TPB / 32)        // 16
#define NBLOCKS 296             // 148 SMs * 2 resident blocks
#define WPB_PER_BATCH ((NBLOCKS / BATCH) * WARPS)        // 1184
#define NPAIRS (NPTS / 2)                                // 2048
#define PPERIOD (NPAIRS + WPB_PER_BATCH)                 // 3232
#define NK ((size_t)NPTS * KOUT)                         // 65536

// steal counters: never reset; pair = ctr % PPERIOD is deterministic/replay
__device__ unsigned g_ctr[BATCH];

// ---- packed f32x2 helpers (per-element .rn == scalar .rn, bit-exact) ----
static __device__ __forceinline__ uint64_t pack2(float a, float b) {
    uint64_t r; asm("mov.b64 %0, {%1, %2};" : "=l"(r) : "f"(a), "f"(b));
    return r;
}
static __device__ __forceinline__ uint64_t mul2(uint64_t a, uint64_t b) {
    uint64_t r; asm("mul.rn.f32x2 %0, %1, %2;" : "=l"(r) : "l"(a), "l"(b));
    return r;
}
static __device__ __forceinline__ uint64_t add2(uint64_t a, uint64_t b) {
    uint64_t r; asm("add.rn.f32x2 %0, %1, %2;" : "=l"(r) : "l"(a), "l"(b));
    return r;
}
static __device__ __forceinline__ void unpack2(uint64_t v, float& lo, float& hi) {
    asm("mov.b64 {%0, %1}, %2;" : "=f"(lo), "=f"(hi) : "l"(v));
}
// d2 for candidate p against packed queries (q0|q1):
// d2 = (qw + pw) + (-2)*((qx*px + qy*py) + qz*pz)   [exact per element]
static __device__ __forceinline__ uint64_t dist2q(
        uint64_t qx2, uint64_t qy2, uint64_t qz2, uint64_t qw2, uint64_t m2c,
        float4 p) {
    uint64_t px = pack2(p.x, p.x);
    uint64_t py = pack2(p.y, p.y);
    uint64_t pz = pack2(p.z, p.z);
    uint64_t pw = pack2(p.w, p.w);
    uint64_t dot = add2(add2(mul2(qx2, px), mul2(qy2, py)), mul2(qz2, pz));
    return add2(add2(qw2, pw), mul2(m2c, dot));
}

// ---------------------------------------------------------------------------
// Fused kernel: paired ball query + dilated selection + gather epilogue.
// Warp per query-PAIR (work-stealing). One candidate scan feeds 2 queries.
// Ballot words live in registers: lane l holds tiles {l,32+l,64+l,96+l}.
// ---------------------------------------------------------------------------
__global__ void __launch_bounds__(TPB, 2) fused_kernel(
        const float* __restrict__ xyz,
        const float* __restrict__ feat,
        float* __restrict__ out) {
    extern __shared__ float4 s[];                       // 4096 float4 = 64KB
    __shared__ int oid[WARPS][2][KOUT + 1];
    __shared__ float4 stage[WARPS][128];                // 16 rows x 8 f4 = 2KB

    int b = blockIdx.x % BATCH;
    const float* xb = xyz + (size_t)b * NPTS * 3;

    for (int i = threadIdx.x; i < NPTS; i += blockDim.x) {
        float x = xb[3 * i + 0];
        float y = xb[3 * i + 1];
        float z = xb[3 * i + 2];
        float nq = __fadd_rn(__fadd_rn(__fmul_rn(x, x), __fmul_rn(y, y)),
                             __fmul_rn(z, z));
        s[i] = make_float4(x, y, z, nq);
    }
    __syncthreads();

    int warp = threadIdx.x >> 5;
    int lane = threadIdx.x & 31;
    const float* fb = feat + (size_t)b * NPTS * 64;
    float* outx = out + ((size_t)b * 3) * NK;                 // xyz block
    float* outf = out + (size_t)BATCH * 3 * NK + ((size_t)b * 64) * NK;
    const uint64_t m2c = pack2(-2.0f, -2.0f);

    for (;;) {
        unsigned pr = 0;
        if (lane == 0) pr = atomicAdd(&g_ctr[b], 1u) % PPERIOD;
        int pi = __shfl_sync(0xffffffffu, (int)pr, 0);
        if (pi >= NPAIRS) break;
        int q0 = 2 * pi;

        float4 a0 = s[q0];
        float4 a1 = s[q0 + 1];
        uint64_t qx2 = pack2(a0.x, a1.x);
        uint64_t qy2 = pack2(a0.y, a1.y);
        uint64_t qz2 = pack2(a0.z, a1.z);
        uint64_t qw2 = pack2(a0.w, a1.w);

        int cnt0 = 0, cnt1 = 0;
        int tscan = NTILES;
        unsigned w0[4] = {0u, 0u, 0u, 0u};
        unsigned w1[4] = {0u, 0u, 0u, 0u};

        // ---- shared scan: 4 tiles (128 candidates) per iteration ----
        {
            const float4* sp = s + lane;
            for (int c = 0; c < NTILES; c += 4, sp += 128) {
                float4 p0 = sp[0];
                float4 p1 = sp[32];
                float4 p2 = sp[64];
                float4 p3 = sp[96];
                uint64_t dd0 = dist2q(qx2, qy2, qz2, qw2, m2c, p0);
                uint64_t dd1 = dist2q(qx2, qy2, qz2, qw2, m2c, p1);
                uint64_t dd2 = dist2q(qx2, qy2, qz2, qw2, m2c, p2);
                uint64_t dd3 = dist2q(qx2, qy2, qz2, qw2, m2c, p3);
                float e0a, e0b, e1a, e1b, e2a, e2b, e3a, e3b;
                unpack2(dd0, e0a, e0b);
                unpack2(dd1, e1a, e1b);
                unpack2(dd2, e2a, e2b);
                unpack2(dd3, e3a, e3b);
                unsigned ma0 = __ballot_sync(0xffffffffu, e0a < R2);
                unsigned ma1 = __ballot_sync(0xffffffffu, e1a < R2);
                unsigned ma2 = __ballot_sync(0xffffffffu, e2a < R2);
                unsigned ma3 = __ballot_sync(0xffffffffu, e3a < R2);
                unsigned mb0 = __ballot_sync(0xffffffffu, e0b < R2);
                unsigned mb1 = __ballot_sync(0xffffffffu, e1b < R2);
                unsigned mb2 = __ballot_sync(0xffffffffu, e2b < R2);
                unsigned mb3 = __ballot_sync(0xffffffffu, e3b < R2);

                // stash masks: lanes (c&31)+j keep tile c+j in reg (c>>5)
                int pos = c & 31;
                unsigned sel = (unsigned)(lane - pos);
                unsigned my0 = (sel == 0) ? ma0 : (sel == 1) ? ma1
                             : (sel == 2) ? ma2 : ma3;
                unsigned my1 = (sel == 0) ? mb0 : (sel == 1) ? mb1
                             : (sel == 2) ? mb2 : mb3;
                bool mine = sel < 4u;
                int g = c >> 5;
#pragma unroll
                for (int gg = 0; gg < 4; gg++)
                    if (gg == g && mine) { w0[gg] = my0; w1[gg] = my1; }

                cnt0 += __popc(ma0) + __popc(ma1) + __popc(ma2) + __popc(ma3);
                cnt1 += __popc(mb0) + __popc(mb1) + __popc(mb2) + __popc(mb3);
                if (cnt0 >= NEED && cnt1 >= NEED) { tscan = c + 4; break; }
            }
        }
        __syncwarp();

        // ---- decode both queries: rank 0 and ranks 16..30 ----
#pragma unroll
        for (int qs = 0; qs < 2; qs++) {
            const unsigned* w = qs ? w1 : w0;
            int base = 0;
#pragma unroll
            for (int g = 0; g < 4; g++) {
                if (base >= NEED) break;
                int wi = 32 * g + lane;
                unsigned ww = (wi < tscan) ? w[g] : 0u;
                int pc = __popc(ww);
                int pre = pc;                      // inclusive warp scan
#pragma unroll
                for (int o = 1; o < 32; o <<= 1) {
                    int t = __shfl_up_sync(0xffffffffu, pre, o);
                    if (lane >= o) pre += t;
                }
                int lo = base + pre - pc;          // first rank in my word
                if (ww && lo < NEED) {
                    unsigned wr = ww;
                    int r = lo;
                    while (wr && r < NEED) {
                        int bit = __ffs(wr) - 1;
                        wr &= wr - 1;
                        if (r == 0)
                            oid[warp][qs][0] = 32 * wi + bit;
                        else if (r >= 16)
                            oid[warp][qs][r - 15] = 32 * wi + bit;
                        r++;
                    }
                }
                base += __shfl_sync(0xffffffffu, pre, 31);
            }
        }
        __syncwarp();

        // ---- per-query finalize + gather epilogue ----
#pragma unroll
        for (int qs = 0; qs < 2; qs++) {
            int q = q0 + qs;
            int cnt = qs ? cnt1 : cnt0;

            if (lane < KOUT) {
                int v = (lane > 0 && cnt >= lane + 16) ? oid[warp][qs][lane]
                                                       : oid[warp][qs][0];
                oid[warp][qs][lane] = v;
            }
            __syncwarp();

            // xyz: straight from smem (lanes 0..15, k = lane)
            if (lane < KOUT) {
                float4 p = s[oid[warp][qs][lane]];
                size_t ox = (size_t)q * KOUT + lane;
                outx[ox]          = p.x;
                outx[ox + NK]     = p.y;
                outx[ox + 2 * NK] = p.z;
            }

            // feat: 2 passes over channel halves; coalesced row loads ->
            // XOR-swizzled stage -> channel-major 64B-segment stores.
            int ldrow = lane >> 3;           // 0..3 row-within-group
            int ldlc  = lane & 7;            // chunk within half
            int k     = lane & 15;
            int sub   = lane >> 4;
#pragma unroll
            for (int p = 0; p < 2; p++) {
#pragma unroll
                for (int i = 0; i < 4; i++) {
                    int row = 4 * i + ldrow;
                    int id = oid[warp][qs][row];
                    float4 v = *((const float4*)(fb + (size_t)id * 64)
                                 + (p * 8 + ldlc));
                    stage[warp][row * 8 + (ldlc ^ (row & 7))] = v;
                }
                __syncwarp();
#pragma unroll
                for (int t = 0; t < 4; t++) {
                    int lc = sub * 4 + t;
                    float4 v = stage[warp][k * 8 + (lc ^ (k & 7))];
                    float* o = outf + (size_t)((p * 8 + lc) * 4) * NK
                                    + (size_t)q * KOUT + k;
                    o[0]      = v.x;
                    o[NK]     = v.y;
                    o[2 * NK] = v.z;
                    o[3 * NK] = v.w;
                }
                __syncwarp();
            }
        }
    }
}

extern "C" void kernel_launch(void* const* d_in, const int* in_sizes, int n_in,
                              void* d_out, int out_size) {
    const float* xyz  = (const float*)d_in[0];
    const float* feat = (const float*)d_in[1];
    float* out = (float*)d_out;

    cudaFuncSetAttribute(fused_kernel,
                         cudaFuncAttributeMaxDynamicSharedMemorySize,
                         NPTS * sizeof(float4));

    fused_kernel<<<NBLOCKS, TPB, NPTS * sizeof(float4)>>>(xyz, feat, out);
}

// round 10
// speedup vs baseline: 1.0699x; 1.0699x over previous
#include <cuda_runtime.h>
#include <cstdint>

#define BATCH 4
#define NPTS 4096
#define KOUT 16
#define NEED 31                 // rank 0 plus ranks 16..30
#define R2 256.0f
#define NTILES (NPTS / 32)      // 128
#define TPB 512
#define WARPS (TPB / 32)        // 16
#define NBLOCKS 296             // 148 SMs * 2 resident blocks
#define WPB_PER_BATCH ((NBLOCKS / BATCH) * WARPS)        // 1184
#define NPAIRS (NPTS / 2)                                // 2048
#define PPERIOD (NPAIRS + WPB_PER_BATCH)                 // 3232
#define NK ((size_t)NPTS * KOUT)                         // 65536
#define NBUCK 512

// steal counters: never reset; pair = ctr % PPERIOD is deterministic/replay.
// g_ord: per-batch query order sorted by r^2 (density proxy). The pairing it
// induces is output-transparent (each query decoded independently).
__device__ unsigned g_ctr[BATCH];
__device__ int g_ord[BATCH * NPTS];

// exact arithmetic (matches reference decisions; rel_err 0.0 with this)
static __device__ __forceinline__ float dist2(float4 a, float4 b) {
    float dot = __fadd_rn(
        __fadd_rn(__fmul_rn(a.x, b.x), __fmul_rn(a.y, b.y)),
        __fmul_rn(a.z, b.z));
    return __fsub_rn(__fadd_rn(a.w, b.w), __fmul_rn(2.0f, dot));
}

static __device__ __forceinline__ unsigned sel4(int d, unsigned a, unsigned b,
                                                unsigned c, unsigned e) {
    unsigned r = (d == 1) ? b : a;
    r = (d == 2) ? c : r;
    r = (d == 3) ? e : r;
    return r;
}

// ---------------------------------------------------------------------------
// Prepass: bucket-sort queries of each batch by r^2 into g_ord.
// Within-bucket order is atomic-arbitrary; outputs do not depend on it.
// ---------------------------------------------------------------------------
__global__ void __launch_bounds__(512) order_kernel(const float* __restrict__ xyz) {
    __shared__ int hist[NBUCK];
    __shared__ int wsum[16];
    int b = blockIdx.x;
    const float* xb = xyz + (size_t)b * NPTS * 3;
    int t = threadIdx.x;
    int lane = t & 31, wid = t >> 5;

    hist[t] = 0;
    __syncthreads();

    int mykey[NPTS / 512];
#pragma unroll
    for (int j = 0; j < NPTS / 512; j++) {
        int i = t + j * 512;
        float x = xb[3 * i], y = xb[3 * i + 1], z = xb[3 * i + 2];
        float r2 = x * x + y * y + z * z;          // heuristic key only
        int k = (int)(r2 * (1.0f / 24.0f));
        k = k < 0 ? 0 : (k > NBUCK - 1 ? NBUCK - 1 : k);
        mykey[j] = k;
        atomicAdd(&hist[k], 1);
    }
    __syncthreads();

    // exclusive prefix over NBUCK buckets (1 per thread)
    int v = hist[t];
    int pre = v;
#pragma unroll
    for (int o = 1; o < 32; o <<= 1) {
        int u = __shfl_up_sync(0xffffffffu, pre, o);
        if (lane >= o) pre += u;
    }
    if (lane == 31) wsum[wid] = pre;
    __syncthreads();
    if (t == 0) {
        int acc = 0;
        for (int i = 0; i < 16; i++) { int tmp = wsum[i]; wsum[i] = acc; acc += tmp; }
    }
    __syncthreads();
    int excl = pre - v + wsum[wid];
    __syncthreads();
    hist[t] = excl;                    // running offsets
    __syncthreads();

#pragma unroll
    for (int j = 0; j < NPTS / 512; j++) {
        int i = t + j * 512;
        int pos = atomicAdd(&hist[mykey[j]], 1);
        g_ord[b * NPTS + pos] = i;
    }
}

// ---------------------------------------------------------------------------
// Fused kernel: paired ball query (shared candidate stream, scalar math) +
// dilated selection + gather epilogue. Warp per sorted-adjacent query pair.
// Ballot masks in registers: lane l holds tile 32g+l in w[g].
// ---------------------------------------------------------------------------
__global__ void __launch_bounds__(TPB, 2) fused_kernel(
        const float* __restrict__ xyz,
        const float* __restrict__ feat,
        float* __restrict__ out) {
    extern __shared__ float4 s[];                       // 4096 float4 = 64KB
    __shared__ int oid[WARPS][2][KOUT + 1];
    __shared__ float4 stage[WARPS][128];                // 16 rows x 8 f4 = 2KB

    int b = blockIdx.x % BATCH;
    const float* xb = xyz + (size_t)b * NPTS * 3;

    for (int i = threadIdx.x; i < NPTS; i += blockDim.x) {
        float x = xb[3 * i + 0];
        float y = xb[3 * i + 1];
        float z = xb[3 * i + 2];
        float nq = __fadd_rn(__fadd_rn(__fmul_rn(x, x), __fmul_rn(y, y)),
                             __fmul_rn(z, z));
        s[i] = make_float4(x, y, z, nq);
    }
    __syncthreads();

    int warp = threadIdx.x >> 5;
    int lane = threadIdx.x & 31;
    const float* fb = feat + (size_t)b * NPTS * 64;
    float* outx = out + ((size_t)b * 3) * NK;                 // xyz block
    float* outf = out + (size_t)BATCH * 3 * NK + ((size_t)b * 64) * NK;
    const int* ordb = g_ord + b * NPTS;

    for (;;) {
        unsigned pr = 0;
        if (lane == 0) pr = atomicAdd(&g_ctr[b], 1u) % PPERIOD;
        int pi = __shfl_sync(0xffffffffu, (int)pr, 0);
        if (pi >= NPAIRS) break;
        int q0 = ordb[2 * pi];
        int q1 = ordb[2 * pi + 1];

        float4 A0 = s[q0];
        float4 A1 = s[q1];

        int cnt0 = 0, cnt1 = 0;
        int tscan = NTILES;
        bool done = false;
        unsigned w0[4] = {0u, 0u, 0u, 0u};
        unsigned w1[4] = {0u, 0u, 0u, 0u};

        // ---- shared scan: 4 tiles / iter; masks stashed into registers ----
        {
            const float4* sp = s + lane;
#pragma unroll
            for (int g = 0; g < 4; g++) {
                if (!done) {
                    for (int s8 = 0; s8 < 8; s8++) {
                        float4 p0 = sp[0];
                        float4 p1 = sp[32];
                        float4 p2 = sp[64];
                        float4 p3 = sp[96];
                        sp += 128;
                        float e00 = dist2(A0, p0), e01 = dist2(A0, p1);
                        float e02 = dist2(A0, p2), e03 = dist2(A0, p3);
                        float e10 = dist2(A1, p0), e11 = dist2(A1, p1);
                        float e12 = dist2(A1, p2), e13 = dist2(A1, p3);
                        unsigned ma0 = __ballot_sync(0xffffffffu, e00 < R2);
                        unsigned ma1 = __ballot_sync(0xffffffffu, e01 < R2);
                        unsigned ma2 = __ballot_sync(0xffffffffu, e02 < R2);
                        unsigned ma3 = __ballot_sync(0xffffffffu, e03 < R2);
                        unsigned mb0 = __ballot_sync(0xffffffffu, e10 < R2);
                        unsigned mb1 = __ballot_sync(0xffffffffu, e11 < R2);
                        unsigned mb2 = __ballot_sync(0xffffffffu, e12 < R2);
                        unsigned mb3 = __ballot_sync(0xffffffffu, e13 < R2);

                        int diff = lane - s8 * 4;
                        unsigned my0 = sel4(diff, ma0, ma1, ma2, ma3);
                        unsigned my1 = sel4(diff, mb0, mb1, mb2, mb3);
                        if ((unsigned)diff < 4u) { w0[g] = my0; w1[g] = my1; }

                        cnt0 += __popc(ma0) + __popc(ma1)
                              + __popc(ma2) + __popc(ma3);
                        cnt1 += __popc(mb0) + __popc(mb1)
                              + __popc(mb2) + __popc(mb3);
                        if (cnt0 >= NEED && cnt1 >= NEED) {
                            tscan = g * 32 + s8 * 4 + 4;
                            done = true;
                            break;
                        }
                    }
                }
            }
        }
        __syncwarp();

        // ---- decode both queries: rank 0 and ranks 16..30 ----
#pragma unroll
        for (int qs = 0; qs < 2; qs++) {
            const unsigned* w = qs ? w1 : w0;
            int base = 0;
#pragma unroll
            for (int g = 0; g < 4; g++) {
                if (base >= NEED) break;
                int wi = 32 * g + lane;
                unsigned ww = (wi < tscan) ? w[g] : 0u;
                int pc = __popc(ww);
                int pre = pc;                      // inclusive warp scan
#pragma unroll
                for (int o = 1; o < 32; o <<= 1) {
                    int t = __shfl_up_sync(0xffffffffu, pre, o);
                    if (lane >= o) pre += t;
                }
                int lo = base + pre - pc;          // first rank in my word
                if (ww && lo < NEED) {
                    unsigned wr = ww;
                    int r = lo;
                    while (wr && r < NEED) {
                        int bit = __ffs(wr) - 1;
                        wr &= wr - 1;
                        if (r == 0)
                            oid[warp][qs][0] = 32 * wi + bit;
                        else if (r >= 16)
                            oid[warp][qs][r - 15] = 32 * wi + bit;
                        r++;
                    }
                }
                base += __shfl_sync(0xffffffffu, pre, 31);
            }
        }
        __syncwarp();

        // ---- per-query finalize + gather epilogue ----
#pragma unroll
        for (int qs = 0; qs < 2; qs++) {
            int q = qs ? q1 : q0;
            int cnt = qs ? cnt1 : cnt0;

            if (lane < KOUT) {
                int v = (lane > 0 && cnt >= lane + 16) ? oid[warp][qs][lane]
                                                       : oid[warp][qs][0];
                oid[warp][qs][lane] = v;
            }
            __syncwarp();

            // xyz: straight from smem (lanes 0..15, k = lane)
            if (lane < KOUT) {
                float4 p = s[oid[warp][qs][lane]];
                size_t ox = (size_t)q * KOUT + lane;
                outx[ox]          = p.x;
                outx[ox + NK]     = p.y;
                outx[ox + 2 * NK] = p.z;
            }

            // feat: 2 passes over channel halves; coalesced row loads ->
            // XOR-swizzled stage -> channel-major 64B-segment stores.
            int ldrow = lane >> 3;           // 0..3 row-within-group
            int ldlc  = lane & 7;            // chunk within half
            int k     = lane & 15;
            int sub   = lane >> 4;
#pragma unroll
            for (int p = 0; p < 2; p++) {
#pragma unroll
                for (int i = 0; i < 4; i++) {
                    int row = 4 * i + ldrow;
                    int id = oid[warp][qs][row];
                    float4 v = *((const float4*)(fb + (size_t)id * 64)
                                 + (p * 8 + ldlc));
                    stage[warp][row * 8 + (ldlc ^ (row & 7))] = v;
                }
                __syncwarp();
#pragma unroll
                for (int t = 0; t < 4; t++) {
                    int lc = sub * 4 + t;
                    float4 v = stage[warp][k * 8 + (lc ^ (k & 7))];
                    float* o = outf + (size_t)((p * 8 + lc) * 4) * NK
                                    + (size_t)q * KOUT + k;
                    o[0]      = v.x;
                    o[NK]     = v.y;
                    o[2 * NK] = v.z;
                    o[3 * NK] = v.w;
                }
                __syncwarp();
            }
        }
    }
}

extern "C" void kernel_launch(void* const* d_in, const int* in_sizes, int n_in,
                              void* d_out, int out_size) {
    const float* xyz  = (const float*)d_in[0];
    const float* feat = (const float*)d_in[1];
    float* out = (float*)d_out;

    cudaFuncSetAttribute(fused_kernel,
                         cudaFuncAttributeMaxDynamicSharedMemorySize,
                         NPTS * sizeof(float4));

    order_kernel<<<BATCH, 512>>>(xyz);
    fused_kernel<<<NBLOCKS, TPB, NPTS * sizeof(float4)>>>(xyz, feat, out);
}